// round 9
// baseline (speedup 1.0000x reference)
#include <cuda_runtime.h>
#include <cuda_bf16.h>

// f  : (B=32, H=512, W=512) f32
// K  : (5, 5, H, W)         f32  (per-pixel kernels, shared over batch -> registers)
// dt : (B,)                 f32
// out = relu(f + conv5x5_perpixel(f) * dt[b])
//
// R8 (= R7 resubmit; infra failure last round):
// 4 px/thread (x) -> 100 fp32 taps in regs, 2x LDS.128 per kernel row per
// batch (40B/px vs 60B/px), 128-thread blocks @ 3 CTAs/SM (170-reg budget),
// NB=4 batch tiles in smem (16 independent FMA chains), cp.async staging with
// zero-fill halo, double-buffered, 1 barrier per pass.

#define B_    32
#define H_    512
#define W_    512
#define HW_   (H_ * W_)
#define KS    5
#define RAD   2
#define TW    32                    // tile width in pixels  (8 threads x 4 px)
#define TH    16                    // tile height in pixels
#define TILE_W (TW + 2*RAD)         // 36
#define TILE_H (TH + 2*RAD)         // 20
#define SSTR   40                   // mult of 4 -> LDS.128-aligned row windows
#define PLANE  (TILE_H * SSTR)      // 800 floats
#define TILE_ELEMS (TILE_W * TILE_H)   // 720
#define NTHR  128
#define NLD   6                     // ceil(720/128)
#define NB    4
#define NPASS (B_ / NB)             // 8

__device__ __forceinline__ void cp4(unsigned sa, const float* g, int sz) {
    // 4-byte async copy; sz=0 -> zero-fill (halo out-of-bounds)
    asm volatile("cp.async.ca.shared.global [%0], [%1], 4, %2;\n"
                 :: "r"(sa), "l"(g), "r"(sz));
}
__device__ __forceinline__ void cp_commit() { asm volatile("cp.async.commit_group;\n" ::); }
__device__ __forceinline__ void cp_wait0()  { asm volatile("cp.async.wait_group 0;\n" ::); }

__global__ __launch_bounds__(NTHR, 3)
void op2d_kernel(const float* __restrict__ f,
                 const float* __restrict__ K,
                 const float* __restrict__ dt,
                 float* __restrict__ out)
{
    __shared__ __align__(16) float buf[2][NB][PLANE];

    const int tid = threadIdx.x;          // 0..127
    const int tx  = tid & 7;              // 0..7  -> 4 px each
    const int ty  = tid >> 3;             // 0..15
    const int bx  = blockIdx.x * TW;
    const int by  = blockIdx.y * TH;
    const int x0  = bx + tx * 4;
    const int y   = by + ty;
    const int pix = y * W_ + x0;          // multiple of 4 -> float4-aligned

    // ---- 25 taps x 4 px in registers, reused across all 32 batches
    float4 kv[KS * KS];
#pragma unroll
    for (int t = 0; t < KS * KS; ++t)
        kv[t] = __ldg((const float4*)(K + t * HW_ + pix));

    // ---- batch-invariant staging coords (cp.async, zero-fill halo)
    int      goff[NLD];
    int      szb [NLD];
    unsigned sadr[NLD];
    bool     inuse[NLD];
    const unsigned sbase = (unsigned)__cvta_generic_to_shared(&buf[0][0][0]);
#pragma unroll
    for (int k = 0; k < NLD; ++k) {
        const int s  = tid + k * NTHR;
        inuse[k] = (s < TILE_ELEMS);
        const int sy = s / TILE_W;
        const int sx = s - sy * TILE_W;
        const int gy = by - RAD + sy;
        const int gx = bx - RAD + sx;
        const bool v = inuse[k] && (unsigned)gy < (unsigned)H_ && (unsigned)gx < (unsigned)W_;
        goff[k] = v ? gy * W_ + gx : 0;
        szb[k]  = v ? 4 : 0;
        sadr[k] = sbase + (unsigned)(sy * SSTR + sx) * 4u;
    }

    // ---- prologue: stage pass 0 into buffer 0
    {
#pragma unroll
        for (int b = 0; b < NB; ++b)
#pragma unroll
            for (int k = 0; k < NLD; ++k)
                if (inuse[k])
                    cp4(sadr[k] + (unsigned)(b * PLANE) * 4u, f + b * HW_ + goff[k], szb[k]);
        cp_commit();
        cp_wait0();
    }
    __syncthreads();

    const int rbase = ty * SSTR + tx * 4;    // 16B-aligned
    int cur = 0;

    for (int pass = 0; pass < NPASS; ++pass) {
        const int nxt = cur ^ 1;

        // -- stage next pass (overlaps with this pass's compute)
        if (pass + 1 < NPASS) {
            const float* fp = f + (pass + 1) * NB * HW_;
            const unsigned boff = (unsigned)(nxt * NB * PLANE) * 4u;
#pragma unroll
            for (int b = 0; b < NB; ++b)
#pragma unroll
                for (int k = 0; k < NLD; ++k)
                    if (inuse[k])
                        cp4(sadr[k] + boff + (unsigned)(b * PLANE) * 4u,
                            fp + b * HW_ + goff[k], szb[k]);
            cp_commit();
        }

        // -- 5x5 per-pixel conv: 4 batches x 4 px = 16 independent chains
        float4 acc[NB], fc[NB];
#pragma unroll
        for (int b = 0; b < NB; ++b)
            acc[b] = make_float4(0.f, 0.f, 0.f, 0.f);

#pragma unroll
        for (int i = 0; i < KS; ++i) {
#pragma unroll
            for (int b = 0; b < NB; ++b) {
                const float* tb = buf[cur][b] + rbase + i * SSTR;
                const float4 ra = *(const float4*)(tb);      // t[0..3]
                const float4 rb = *(const float4*)(tb + 4);  // t[4..7]
                if (i == RAD) fc[b] = make_float4(ra.z, ra.w, rb.x, rb.y);

                const float4 k0 = kv[i*KS+0], k1 = kv[i*KS+1], k2 = kv[i*KS+2];
                const float4 k3 = kv[i*KS+3], k4 = kv[i*KS+4];
                // px p (0..3) uses window element t[p+j] for tap column j
                acc[b].x = fmaf(k0.x, ra.x, acc[b].x);
                acc[b].y = fmaf(k0.y, ra.y, acc[b].y);
                acc[b].z = fmaf(k0.z, ra.z, acc[b].z);
                acc[b].w = fmaf(k0.w, ra.w, acc[b].w);

                acc[b].x = fmaf(k1.x, ra.y, acc[b].x);
                acc[b].y = fmaf(k1.y, ra.z, acc[b].y);
                acc[b].z = fmaf(k1.z, ra.w, acc[b].z);
                acc[b].w = fmaf(k1.w, rb.x, acc[b].w);

                acc[b].x = fmaf(k2.x, ra.z, acc[b].x);
                acc[b].y = fmaf(k2.y, ra.w, acc[b].y);
                acc[b].z = fmaf(k2.z, rb.x, acc[b].z);
                acc[b].w = fmaf(k2.w, rb.y, acc[b].w);

                acc[b].x = fmaf(k3.x, ra.w, acc[b].x);
                acc[b].y = fmaf(k3.y, rb.x, acc[b].y);
                acc[b].z = fmaf(k3.z, rb.y, acc[b].z);
                acc[b].w = fmaf(k3.w, rb.z, acc[b].w);

                acc[b].x = fmaf(k4.x, rb.x, acc[b].x);
                acc[b].y = fmaf(k4.y, rb.y, acc[b].y);
                acc[b].z = fmaf(k4.z, rb.z, acc[b].z);
                acc[b].w = fmaf(k4.w, rb.w, acc[b].w);
            }
        }

        // -- epilogue: out = relu(fc + acc*dt), coalesced float4 store
        const int b0 = pass * NB;
        const float4 dt4 = __ldg((const float4*)(dt + b0));
        const float dts[NB] = {dt4.x, dt4.y, dt4.z, dt4.w};
#pragma unroll
        for (int b = 0; b < NB; ++b) {
            const float dtb = dts[b];
            float4 o;
            o.x = fmaxf(fmaf(acc[b].x, dtb, fc[b].x), 0.0f);
            o.y = fmaxf(fmaf(acc[b].y, dtb, fc[b].y), 0.0f);
            o.z = fmaxf(fmaf(acc[b].z, dtb, fc[b].z), 0.0f);
            o.w = fmaxf(fmaf(acc[b].w, dtb, fc[b].w), 0.0f);
            *(float4*)(out + (b0 + b) * HW_ + pix) = o;
        }

        if (pass + 1 < NPASS) cp_wait0();
        __syncthreads();
        cur = nxt;
    }
}

extern "C" void kernel_launch(void* const* d_in, const int* in_sizes, int n_in,
                              void* d_out, int out_size)
{
    const float* f  = (const float*)d_in[0];
    const float* K  = (const float*)d_in[1];
    const float* dt = (const float*)d_in[2];
    float* out = (float*)d_out;

    dim3 grid(W_ / TW, H_ / TH);   // 16 x 32 = 512 blocks
    dim3 block(NTHR);
    op2d_kernel<<<grid, block>>>(f, K, dt, out);
}

// round 10
// speedup vs baseline: 1.3884x; 1.3884x over previous
#include <cuda_runtime.h>
#include <cuda_bf16.h>

// f  : (B=32, H=512, W=512) f32
// K  : (5, 5, H, W)         f32  -> bf16x2 taps in regs (shared over batch)
// dt : (B,)                 f32
// out = relu(f + conv5x5_perpixel(f) * dt[b]),  center f kept exact fp32.
//
// R9: bf16 data path. f tiles bf16 in smem (half crossbar bytes), HFMA2
// (2 MAC/instr), 4 px/thread as 2 bf16x2 pairs, 50 tap regs, 128-thr CTAs
// @ 5/SM, NB=4 batch planes per pass, LDG->cvt->STS staging with the LDG
// batch issued before the barrier.

#define B_     32
#define H_     512
#define W_     512
#define HW_    (H_ * W_)
#define KS     5
#define RAD    2
#define TW     32                  // tile width px  (8 thr x 4 px)
#define TH     16                  // tile height px
#define TILE_W 36
#define TILE_H 20
#define SSTRB  192                 // bytes per smem tile row (96 bf16 slots)
#define PLANEB (TILE_H * SSTRB)    // 3840 B per batch plane
#define NB     4
#define NPASS  (B_ / NB)           // 8
#define NTHR   128

union U32B2 { unsigned u; __nv_bfloat162 b; };
__device__ __forceinline__ __nv_bfloat162 u2b(unsigned u) { U32B2 c; c.u = u; return c.b; }
__device__ __forceinline__ unsigned b2u(__nv_bfloat162 b) { U32B2 c; c.b = b; return c.u; }

__global__ __launch_bounds__(NTHR, 5)
void op2d_kernel(const float* __restrict__ f,
                 const float* __restrict__ K,
                 const float* __restrict__ dt,
                 float* __restrict__ out)
{
    __shared__ __align__(16) unsigned char sbuf[NB * PLANEB];   // 15360 B

    const int tid = threadIdx.x;        // 0..127
    const int txc = tid & 7;            // 4 px each
    const int ty  = tid >> 3;           // 0..15
    const int bx  = blockIdx.x * TW;
    const int by  = blockIdx.y * TH;
    const int x0  = bx + txc * 4;
    const int y   = by + ty;
    const int pix = y * W_ + x0;        // 16B-aligned

    // ---- 25 taps x 4 px, packed as 2x bf16x2 per tap (50 regs total)
    __nv_bfloat162 kvA[25], kvB[25];
#pragma unroll
    for (int t = 0; t < 25; ++t) {
        const float4 k4 = __ldg((const float4*)(K + t * HW_ + pix));
        kvA[t] = __floats2bfloat162_rn(k4.x, k4.y);   // px0, px1
        kvB[t] = __floats2bfloat162_rn(k4.z, k4.w);   // px2, px3
    }

    // ---- staging map: 126 threads cover 18 col-pairs x rows {r0, r0+7, r0+14}
    const int  c      = tid % 18;                 // pair column (sx = 2c, 2c+1)
    const int  r0     = tid / 18;                 // 0..7 (7 unused via st_act)
    const bool st_act = (tid < 126);
    const int  gx0    = bx - 2 + 2 * c;           // even -> float2-aligned
    const bool vx     = (unsigned)gx0 < (unsigned)W_;   // pair fully in or out

    int  rr[3]; bool vv[3];
#pragma unroll
    for (int it = 0; it < 3; ++it) {
        const int r  = r0 + 7 * it;
        const int gy = by - 2 + r;
        rr[it] = r;
        vv[it] = st_act && (r < TILE_H) && vx && ((unsigned)gy < (unsigned)H_);
    }

    const int rbyte0 = ty * SSTRB + txc * 8;      // window byte base (8B aligned)

    for (int pass = 0; pass < NPASS; ++pass) {
        const int b0 = pass * NB;

        // -- issue staging LDGs BEFORE the barrier (latency overlaps prev tail)
        float2 v[NB * 3];
#pragma unroll
        for (int b = 0; b < NB; ++b) {
            const float* fp = f + (b0 + b) * HW_;
#pragma unroll
            for (int it = 0; it < 3; ++it)
                v[b * 3 + it] = vv[it]
                    ? *(const float2*)(fp + (by - 2 + rr[it]) * W_ + gx0)
                    : make_float2(0.0f, 0.0f);
        }

        __syncthreads();      // previous pass's compute done -> buf reusable

        // -- convert + store bf16 tiles
#pragma unroll
        for (int b = 0; b < NB; ++b)
#pragma unroll
            for (int it = 0; it < 3; ++it)
                if (st_act && rr[it] < TILE_H)
                    *(__nv_bfloat162*)(sbuf + b * PLANEB + rr[it] * SSTRB + c * 4)
                        = __floats2bfloat162_rn(v[b * 3 + it].x, v[b * 3 + it].y);

        __syncthreads();

        // -- exact fp32 center + dt (L2-hit: planes just staged)
        float4 c4[NB];
#pragma unroll
        for (int b = 0; b < NB; ++b)
            c4[b] = __ldg((const float4*)(f + (b0 + b) * HW_ + pix));
        const float4 dt4 = __ldg((const float4*)(dt + b0));
        const float dts[4] = { dt4.x, dt4.y, dt4.z, dt4.w };

        // -- 5x5 conv, bf16 HFMA2: pairs A=(px0,px1), B=(px2,px3); 8 chains
        __nv_bfloat162 accA[NB], accB[NB];
        const __nv_bfloat162 z2 = __floats2bfloat162_rn(0.0f, 0.0f);
#pragma unroll
        for (int b = 0; b < NB; ++b) { accA[b] = z2; accB[b] = z2; }

#pragma unroll
        for (int i = 0; i < KS; ++i) {
#pragma unroll
            for (int b = 0; b < NB; ++b) {
                const unsigned char* p = sbuf + b * PLANEB + i * SSTRB + rbyte0;
                const uint2 lo = *(const uint2*)(p);       // (t0,t1),(t2,t3)
                const uint2 hi = *(const uint2*)(p + 8);   // (t4,t5),(t6,t7)
                const unsigned w01 = lo.x, w23 = lo.y, w45 = hi.x, w67 = hi.y;
                const unsigned w12 = __byte_perm(w01, w23, 0x5432);
                const unsigned w34 = __byte_perm(w23, w45, 0x5432);
                const unsigned w56 = __byte_perm(w45, w67, 0x5432);

                accA[b] = __hfma2(kvA[i*5+0], u2b(w01), accA[b]);
                accA[b] = __hfma2(kvA[i*5+1], u2b(w12), accA[b]);
                accA[b] = __hfma2(kvA[i*5+2], u2b(w23), accA[b]);
                accA[b] = __hfma2(kvA[i*5+3], u2b(w34), accA[b]);
                accA[b] = __hfma2(kvA[i*5+4], u2b(w45), accA[b]);

                accB[b] = __hfma2(kvB[i*5+0], u2b(w23), accB[b]);
                accB[b] = __hfma2(kvB[i*5+1], u2b(w34), accB[b]);
                accB[b] = __hfma2(kvB[i*5+2], u2b(w45), accB[b]);
                accB[b] = __hfma2(kvB[i*5+3], u2b(w56), accB[b]);
                accB[b] = __hfma2(kvB[i*5+4], u2b(w67), accB[b]);
            }
        }

        // -- epilogue: bf16 acc -> fp32 (<<16 / mask), out = relu(fc + acc*dt)
#pragma unroll
        for (int b = 0; b < NB; ++b) {
            const unsigned ua = b2u(accA[b]);
            const unsigned ub = b2u(accB[b]);
            const float a0 = __uint_as_float(ua << 16);
            const float a1 = __uint_as_float(ua & 0xFFFF0000u);
            const float a2 = __uint_as_float(ub << 16);
            const float a3 = __uint_as_float(ub & 0xFFFF0000u);
            const float dtb = dts[b];
            float4 o;
            o.x = fmaxf(fmaf(a0, dtb, c4[b].x), 0.0f);
            o.y = fmaxf(fmaf(a1, dtb, c4[b].y), 0.0f);
            o.z = fmaxf(fmaf(a2, dtb, c4[b].z), 0.0f);
            o.w = fmaxf(fmaf(a3, dtb, c4[b].w), 0.0f);
            *(float4*)(out + (b0 + b) * HW_ + pix) = o;
        }
    }
}

extern "C" void kernel_launch(void* const* d_in, const int* in_sizes, int n_in,
                              void* d_out, int out_size)
{
    const float* f  = (const float*)d_in[0];
    const float* K  = (const float*)d_in[1];
    const float* dt = (const float*)d_in[2];
    float* out = (float*)d_out;

    dim3 grid(W_ / TW, H_ / TH);   // 16 x 32 = 512 CTAs
    dim3 block(NTHR);
    op2d_kernel<<<grid, block>>>(f, K, dt, out);
}

// round 12
// speedup vs baseline: 1.5038x; 1.0831x over previous
#include <cuda_runtime.h>
#include <cuda_bf16.h>

// f  : (B=32, H=512, W=512) f32
// K  : (5, 5, H, W)         f32  -> bf16x2 taps in regs (shared over batch)
// dt : (B,)                 f32
// out = relu(f + conv5x5_perpixel(f) * dt[b]),  center f kept exact fp32.
//
// R11 (= R10 resubmit; infra failure last round):
//  - grid.z = 2: each CTA handles 16 batches (4 passes) -> 1024 CTAs, two
//    balanced waves of 4/SM, K taps re-read from L2.
//  - double-buffered smem tiles -> ONE barrier per pass; LDG(p+1) latency
//    hides under compute(p).
//  - fp32->bf16x2 conversion at LDG-return (prefetch carries 12 uints).

#define B_     32
#define H_     512
#define W_     512
#define HW_    (H_ * W_)
#define KS     5
#define RAD    2
#define TW     32                  // tile width px  (8 thr x 4 px)
#define TH     16                  // tile height px
#define TILE_W 36
#define TILE_H 20
#define SSTRB  192                 // bytes per smem tile row (96 bf16 slots)
#define PLANEB (TILE_H * SSTRB)    // 3840 B per batch plane
#define NB     4
#define BSPLIT 2                   // batch split over grid.z
#define NPASS  (B_ / BSPLIT / NB)  // 4
#define NTHR   128

union U32B2 { unsigned u; __nv_bfloat162 b; };
__device__ __forceinline__ __nv_bfloat162 u2b(unsigned u) { U32B2 c; c.u = u; return c.b; }
__device__ __forceinline__ unsigned b2u(__nv_bfloat162 b) { U32B2 c; c.b = b; return c.u; }

__global__ __launch_bounds__(NTHR, 4)
void op2d_kernel(const float* __restrict__ f,
                 const float* __restrict__ K,
                 const float* __restrict__ dt,
                 float* __restrict__ out)
{
    __shared__ __align__(16) unsigned char sbuf[2][NB * PLANEB];   // 2x15360 B

    const int tid = threadIdx.x;        // 0..127
    const int txc = tid & 7;            // 4 px each
    const int ty  = tid >> 3;           // 0..15
    const int bx  = blockIdx.x * TW;
    const int by  = blockIdx.y * TH;
    const int x0  = bx + txc * 4;
    const int y   = by + ty;
    const int pix = y * W_ + x0;        // 16B-aligned
    const int bb0 = blockIdx.z * (B_ / BSPLIT);   // first batch for this CTA

    // ---- 25 taps x 4 px, packed as 2x bf16x2 per tap (50 regs)
    __nv_bfloat162 kvA[25], kvB[25];
#pragma unroll
    for (int t = 0; t < 25; ++t) {
        const float4 k4 = __ldg((const float4*)(K + t * HW_ + pix));
        kvA[t] = __floats2bfloat162_rn(k4.x, k4.y);   // px0, px1
        kvB[t] = __floats2bfloat162_rn(k4.z, k4.w);   // px2, px3
    }

    // ---- staging map: 126 threads cover 18 col-pairs x rows {r0, r0+7, r0+14}
    const int  c      = tid % 18;                 // pair column (sx = 2c, 2c+1)
    const int  r0     = tid / 18;                 // 0..7
    const bool st_act = (tid < 126);
    const int  gx0    = bx - 2 + 2 * c;           // even -> float2-aligned
    const bool vx     = (unsigned)gx0 < (unsigned)W_;

    int  rr[3]; bool vv[3]; bool su[3]; const float* gp[3]; unsigned sp[3];
#pragma unroll
    for (int it = 0; it < 3; ++it) {
        const int r  = r0 + 7 * it;
        const int gy = by - 2 + r;
        rr[it] = r;
        su[it] = st_act && (r < TILE_H);
        vv[it] = su[it] && vx && ((unsigned)gy < (unsigned)H_);
        gp[it] = f + (vv[it] ? (bb0 * HW_ + gy * W_ + gx0) : 0);
        sp[it] = (unsigned)(rr[it] * SSTRB + c * 4);
    }

    const int rbyte0 = ty * SSTRB + txc * 8;      // window byte base

    // ---- prologue: stage pass 0 into buffer 0
    unsigned pre[NB * 3];
#pragma unroll
    for (int b = 0; b < NB; ++b)
#pragma unroll
        for (int it = 0; it < 3; ++it) {
            float2 v = vv[it] ? *(const float2*)(gp[it] + b * HW_)
                              : make_float2(0.0f, 0.0f);
            pre[b * 3 + it] = b2u(__floats2bfloat162_rn(v.x, v.y));
        }
#pragma unroll
    for (int b = 0; b < NB; ++b)
#pragma unroll
        for (int it = 0; it < 3; ++it)
            if (su[it])
                *(unsigned*)(sbuf[0] + b * PLANEB + sp[it]) = pre[b * 3 + it];
    __syncthreads();

    int cur = 0;

    for (int pass = 0; pass < NPASS; ++pass) {
        const int b0  = bb0 + pass * NB;
        const int nxt = cur ^ 1;

        // -- prefetch pass+1 (LDG latency hidden under this pass's compute)
        if (pass + 1 < NPASS) {
            const long poff = (long)(pass + 1) * NB * HW_;
#pragma unroll
            for (int b = 0; b < NB; ++b)
#pragma unroll
                for (int it = 0; it < 3; ++it) {
                    float2 v = vv[it]
                        ? *(const float2*)(gp[it] + poff + b * HW_)
                        : make_float2(0.0f, 0.0f);
                    pre[b * 3 + it] = b2u(__floats2bfloat162_rn(v.x, v.y));
                }
        }

        // -- 5x5 conv, bf16 HFMA2: pairs A=(px0,px1), B=(px2,px3); 8 chains
        __nv_bfloat162 accA[NB], accB[NB];
        const __nv_bfloat162 z2 = __floats2bfloat162_rn(0.0f, 0.0f);
#pragma unroll
        for (int b = 0; b < NB; ++b) { accA[b] = z2; accB[b] = z2; }

#pragma unroll
        for (int i = 0; i < KS; ++i) {
#pragma unroll
            for (int b = 0; b < NB; ++b) {
                const unsigned char* p = sbuf[cur] + b * PLANEB + i * SSTRB + rbyte0;
                const uint2 lo = *(const uint2*)(p);       // (t0,t1),(t2,t3)
                const uint2 hi = *(const uint2*)(p + 8);   // (t4,t5),(t6,t7)
                const unsigned w01 = lo.x, w23 = lo.y, w45 = hi.x, w67 = hi.y;
                const unsigned w12 = __byte_perm(w01, w23, 0x5432);
                const unsigned w34 = __byte_perm(w23, w45, 0x5432);
                const unsigned w56 = __byte_perm(w45, w67, 0x5432);

                accA[b] = __hfma2(kvA[i*5+0], u2b(w01), accA[b]);
                accA[b] = __hfma2(kvA[i*5+1], u2b(w12), accA[b]);
                accA[b] = __hfma2(kvA[i*5+2], u2b(w23), accA[b]);
                accA[b] = __hfma2(kvA[i*5+3], u2b(w34), accA[b]);
                accA[b] = __hfma2(kvA[i*5+4], u2b(w45), accA[b]);

                accB[b] = __hfma2(kvB[i*5+0], u2b(w23), accB[b]);
                accB[b] = __hfma2(kvB[i*5+1], u2b(w34), accB[b]);
                accB[b] = __hfma2(kvB[i*5+2], u2b(w45), accB[b]);
                accB[b] = __hfma2(kvB[i*5+3], u2b(w56), accB[b]);
                accB[b] = __hfma2(kvB[i*5+4], u2b(w67), accB[b]);
            }
        }

        // -- epilogue: exact fp32 center (L2-hit), out = relu(fc + acc*dt)
        const float4 dt4 = __ldg((const float4*)(dt + b0));
        const float dts[4] = { dt4.x, dt4.y, dt4.z, dt4.w };
#pragma unroll
        for (int b = 0; b < NB; ++b) {
            const float4 c4 = __ldg((const float4*)(f + (b0 + b) * HW_ + pix));
            const unsigned ua = b2u(accA[b]);
            const unsigned ub = b2u(accB[b]);
            const float a0 = __uint_as_float(ua << 16);
            const float a1 = __uint_as_float(ua & 0xFFFF0000u);
            const float a2 = __uint_as_float(ub << 16);
            const float a3 = __uint_as_float(ub & 0xFFFF0000u);
            const float dtb = dts[b];
            float4 o;
            o.x = fmaxf(fmaf(a0, dtb, c4.x), 0.0f);
            o.y = fmaxf(fmaf(a1, dtb, c4.y), 0.0f);
            o.z = fmaxf(fmaf(a2, dtb, c4.z), 0.0f);
            o.w = fmaxf(fmaf(a3, dtb, c4.w), 0.0f);
            *(float4*)(out + (b0 + b) * HW_ + pix) = o;
        }

        // -- commit prefetched tiles into the other buffer, single barrier
        if (pass + 1 < NPASS) {
#pragma unroll
            for (int b = 0; b < NB; ++b)
#pragma unroll
                for (int it = 0; it < 3; ++it)
                    if (su[it])
                        *(unsigned*)(sbuf[nxt] + b * PLANEB + sp[it]) = pre[b * 3 + it];
        }
        __syncthreads();
        cur = nxt;
    }
}

extern "C" void kernel_launch(void* const* d_in, const int* in_sizes, int n_in,
                              void* d_out, int out_size)
{
    const float* f  = (const float*)d_in[0];
    const float* K  = (const float*)d_in[1];
    const float* dt = (const float*)d_in[2];
    float* out = (float*)d_out;

    dim3 grid(W_ / TW, H_ / TH, BSPLIT);   // 16 x 32 x 2 = 1024 CTAs
    dim3 block(NTHR);
    op2d_kernel<<<grid, block>>>(f, K, dt, out);
}